// round 8
// baseline (speedup 1.0000x reference)
#include <cuda_runtime.h>
#include <cstdint>

#define BB 8
#define LL 2048
#define DD 256
#define BM 64
#define BN 64
#define NT (LL / BN)

// ---- global scratch (allocation-free device arrays) ----
__device__ float    g_yf[(size_t)BB * LL * DD];     // tf32(x*wp)
__device__ float    g_h [(size_t)BB * LL * 512];    // [tf32(x) | tf32(attn)]
__device__ uint32_t g_xT[(size_t)BB * 256 * 1024];  // x^T bf16 j-pairs
__device__ float    g_su[(size_t)BB * LL];
__device__ float    g_wtf[3 * 256 * 512];           // W^T tf32 [m][n][k]

// ---- helpers ----
__device__ __forceinline__ uint32_t smem_u32(const void* p) {
    uint32_t a;
    asm("{ .reg .u64 t; cvta.to.shared.u64 t, %1; cvt.u32.u64 %0, t; }" : "=r"(a) : "l"(p));
    return a;
}
__device__ __forceinline__ uint32_t pk(float lo, float hi) {
    uint32_t r; asm("cvt.rn.bf16x2.f32 %0, %1, %2;" : "=r"(r) : "f"(hi), "f"(lo)); return r;
}
__device__ __forceinline__ float f2tf(float f) {
    uint32_t u; asm("cvt.rna.tf32.f32 %0, %1;" : "=r"(u) : "f"(f)); return __uint_as_float(u);
}
__device__ __forceinline__ void cpa16(uint32_t dst, const void* src) {
    asm volatile("cp.async.ca.shared.global [%0], [%1], 16;" :: "r"(dst), "l"(src));
}
#define CP_COMMIT() asm volatile("cp.async.commit_group;")
#define CP_WAIT0()  asm volatile("cp.async.wait_group 0;")

__device__ __forceinline__ void mma_bf16(float* c, const uint32_t* a, const uint32_t* b) {
    asm volatile("mma.sync.aligned.m16n8k16.row.col.f32.bf16.bf16.f32 "
        "{%0,%1,%2,%3}, {%4,%5,%6,%7}, {%8,%9}, {%0,%1,%2,%3};"
        : "+f"(c[0]), "+f"(c[1]), "+f"(c[2]), "+f"(c[3])
        : "r"(a[0]), "r"(a[1]), "r"(a[2]), "r"(a[3]), "r"(b[0]), "r"(b[1]));
}
__device__ __forceinline__ void mma_tf32(float* c, const uint32_t* a, const uint32_t* b) {
    asm volatile("mma.sync.aligned.m16n8k8.row.col.f32.tf32.tf32.f32 "
        "{%0,%1,%2,%3}, {%4,%5,%6,%7}, {%8,%9}, {%0,%1,%2,%3};"
        : "+f"(c[0]), "+f"(c[1]), "+f"(c[2]), "+f"(c[3])
        : "r"(a[0]), "r"(a[1]), "r"(a[2]), "r"(a[3]), "r"(b[0]), "r"(b[1]));
}

// ===========================================================================
// prep kernels (unchanged from R7)
// ===========================================================================
__global__ void prep_su(const float* __restrict__ x, const float* __restrict__ w_itr) {
    int row = blockIdx.x * 8 + (threadIdx.x >> 5);
    int lane = threadIdx.x & 31;
    const float* xr = x + (size_t)row * DD;
    float s = 0.f;
    #pragma unroll
    for (int k = 0; k < 8; k++) s += xr[lane + 32 * k] * w_itr[lane + 32 * k];
    #pragma unroll
    for (int off = 16; off > 0; off >>= 1) s += __shfl_xor_sync(0xffffffffu, s, off);
    if (lane == 0) g_su[row] = s;
}

__global__ void prep_pack(const float* __restrict__ x, const float* __restrict__ w_itr) {
    __shared__ float tl[64][65];
    int blk = blockIdx.x;                      // b*128 + jt*4 + dt
    int b = blk >> 7, rem = blk & 127, jt = rem >> 2, dt = rem & 3;
    int j0 = jt * 64, d0 = dt * 64;
    const float* xb = x + ((size_t)b * LL + j0) * DD + d0;
    int tid = threadIdx.x;
    #pragma unroll
    for (int p = 0; p < 4; p++) {
        int idx = tid + p * 256;
        int r = idx >> 4, c4 = idx & 15;
        float4 v = *(const float4*)(xb + (size_t)r * DD + c4 * 4);
        tl[r][c4 * 4 + 0] = v.x; tl[r][c4 * 4 + 1] = v.y;
        tl[r][c4 * 4 + 2] = v.z; tl[r][c4 * 4 + 3] = v.w;
    }
    __syncthreads();
    const float* wp = w_itr + 2 * DD;
    #pragma unroll
    for (int p = 0; p < 4; p++) {
        int idx = tid + p * 256;
        int r = idx >> 4, c4 = idx & 15;
        float a0 = tl[r][c4 * 4 + 0], a1 = tl[r][c4 * 4 + 1];
        float a2 = tl[r][c4 * 4 + 2], a3 = tl[r][c4 * 4 + 3];
        float4 y, h;
        y.x = f2tf(a0 * wp[d0 + c4 * 4 + 0]); y.y = f2tf(a1 * wp[d0 + c4 * 4 + 1]);
        y.z = f2tf(a2 * wp[d0 + c4 * 4 + 2]); y.w = f2tf(a3 * wp[d0 + c4 * 4 + 3]);
        h.x = f2tf(a0); h.y = f2tf(a1); h.z = f2tf(a2); h.w = f2tf(a3);
        *(float4*)(g_yf + ((size_t)b * LL + j0 + r) * DD + d0 + c4 * 4) = y;
        *(float4*)(g_h  + ((size_t)b * LL + j0 + r) * 512 + d0 + c4 * 4) = h;
    }
    #pragma unroll
    for (int p = 0; p < 8; p++) {
        int idx = tid + p * 256;
        int dl = idx >> 5, jw = idx & 31;
        g_xT[((size_t)b * 256 + d0 + dl) * 1024 + (j0 >> 1) + jw] =
            pk(tl[2 * jw][dl], tl[2 * jw + 1][dl]);
    }
}

__global__ void prep_w(const float* __restrict__ w1, const float* __restrict__ w2,
                       const float* __restrict__ w3) {
    __shared__ float tl[64][65];
    int blk = blockIdx.x;                        // m*32 + kt*4 + nt
    int m = blk >> 5, rem = blk & 31, kt = rem >> 2, nt = rem & 3;
    int k0 = kt * 64, n0 = nt * 64;
    const float* W = (m == 0) ? w1 : (m == 1) ? w2 : w3;
    int tid = threadIdx.x;
    #pragma unroll
    for (int p = 0; p < 4; p++) {
        int idx = tid + p * 256;
        int r = idx >> 4, c4 = idx & 15;
        float4 v = *(const float4*)(W + (size_t)(k0 + r) * DD + n0 + c4 * 4);
        tl[r][c4 * 4 + 0] = v.x; tl[r][c4 * 4 + 1] = v.y;
        tl[r][c4 * 4 + 2] = v.z; tl[r][c4 * 4 + 3] = v.w;
    }
    __syncthreads();
    #pragma unroll
    for (int p = 0; p < 4; p++) {
        int idx = tid + p * 256;
        int nl = idx >> 4, kc4 = idx & 15;
        float4 o;
        o.x = f2tf(tl[kc4 * 4 + 0][nl]); o.y = f2tf(tl[kc4 * 4 + 1][nl]);
        o.z = f2tf(tl[kc4 * 4 + 2][nl]); o.w = f2tf(tl[kc4 * 4 + 3][nl]);
        *(float4*)(g_wtf + ((size_t)m * 256 + n0 + nl) * 512 + k0 + kc4 * 4) = o;
    }
}

// ===========================================================================
// attention, 512 threads / 16 warps.
// S grid 2x8 (warp: 32 rows x 8 cols), PV grid 4x4 (warp: 64 d x 16 i).
// K tile cp.async'd during PV phase; Kt/su double-buffered.
// ===========================================================================
#define A_SU  0        // [2][64] f32
#define A_INV 512      // [64] f32
#define A_LSP 768      // [8][64] f32
#define A_YS  2816     // [64][260] f32
#define A_KS  69376    // [64][260] f32 (single buffer)
#define A_KT  135936   // [2][256][36] u32
#define A_PS  209664   // [64][36] u32
#define A_END 218880

__global__ __launch_bounds__(512, 1) void attn_kernel() {
    extern __shared__ char smem[];
    const uint32_t sb = smem_u32(smem);
    float* su_s  = (float*)(smem + A_SU);
    float* inv_s = (float*)(smem + A_INV);
    float* lsp   = (float*)(smem + A_LSP);
    const uint32_t* Ysw = (const uint32_t*)(smem + A_YS);
    const uint32_t* Ksw = (const uint32_t*)(smem + A_KS);
    const uint32_t* Ktw = (const uint32_t*)(smem + A_KT);
    uint32_t* Pw = (uint32_t*)(smem + A_PS);

    const int tid = threadIdx.x, w = tid >> 5, lane = tid & 31;
    const int g = lane >> 2, t = lane & 3;
    const int wsr = w & 1, wsc = w >> 1;      // S grid 2x8
    const int wor = w & 3, woc = w >> 2;      // PV grid 4x4
    const int b = blockIdx.y, q0 = blockIdx.x * BM;
    const int bbase = b * LL;

    // ---- preamble: cp.async Y, K(0), Kt(0), su(0) ----
    #pragma unroll
    for (int p = 0; p < 8; p++) {
        int idx = tid + p * 512;
        int r = idx >> 6, c4 = idx & 63;
        cpa16(sb + A_YS + (r * 260 + c4 * 4) * 4,
              &g_yf[((size_t)(bbase + q0 + r)) * DD + c4 * 4]);
    }
    #pragma unroll
    for (int p = 0; p < 8; p++) {
        int idx = tid + p * 512;
        int r = idx >> 6, c4 = idx & 63;
        cpa16(sb + A_KS + (r * 260 + c4 * 4) * 4,
              &g_h[((size_t)(bbase + r)) * 512 + c4 * 4]);
    }
    #pragma unroll
    for (int p = 0; p < 4; p++) {
        int idx = tid + p * 512;
        int d = idx >> 3, c = idx & 7;
        cpa16(sb + A_KT + (d * 36 + c * 4) * 4,
              &g_xT[((size_t)(b * 256 + d)) * 1024 + c * 4]);
    }
    if (tid < 16) cpa16(sb + A_SU + tid * 16, &g_su[bbase + tid * 4]);
    CP_COMMIT();

    float accO[4][2][4];
    #pragma unroll
    for (int mi = 0; mi < 4; mi++)
        #pragma unroll
        for (int ni = 0; ni < 2; ni++)
            #pragma unroll
            for (int q = 0; q < 4; q++) accO[mi][ni][q] = 0.f;
    float lsum[2][2] = {{0.f, 0.f}, {0.f, 0.f}};

    for (int tt = 0; tt < NT; tt++) {
        CP_WAIT0();
        __syncthreads();                 // Y/K(tt)/Kt(tt)/su(tt) ready; prior PV done
        const int buf = tt & 1;

        if (tt < NT - 1) {               // prefetch Kt(t+1)/su(t+1)
            const int nb = (tt + 1) & 1, j1 = (tt + 1) * BN;
            #pragma unroll
            for (int p = 0; p < 4; p++) {
                int idx = tid + p * 512;
                int d = idx >> 3, c = idx & 7;
                cpa16(sb + A_KT + nb * 36864 + (d * 36 + c * 4) * 4,
                      &g_xT[((size_t)(b * 256 + d)) * 1024 + (j1 >> 1) + c * 4]);
            }
            if (tid < 16) cpa16(sb + A_SU + nb * 256 + tid * 16, &g_su[bbase + j1 + tid * 4]);
            CP_COMMIT();
        }

        // ---- S = Y @ K^T : tf32, warp tile 32x8, K=256 ----
        float accS[2][4];
        #pragma unroll
        for (int mi = 0; mi < 2; mi++)
            #pragma unroll
            for (int q = 0; q < 4; q++) accS[mi][q] = 0.f;
        #pragma unroll 8
        for (int ks = 0; ks < 32; ks++) {
            const int d0 = ks * 8;
            uint32_t a[2][4], bf[2];
            #pragma unroll
            for (int mi = 0; mi < 2; mi++) {
                const uint32_t* yp = Ysw + (wsr * 32 + mi * 16 + g) * 260 + d0 + t;
                a[mi][0] = yp[0]; a[mi][1] = yp[8 * 260];
                a[mi][2] = yp[4]; a[mi][3] = yp[8 * 260 + 4];
            }
            {
                const uint32_t* kp = Ksw + (wsc * 8 + g) * 260 + d0 + t;
                bf[0] = kp[0]; bf[1] = kp[4];
            }
            mma_tf32(accS[0], a[0], bf);
            mma_tf32(accS[1], a[1], bf);
        }

        // ---- epilogue: P = bf16(exp(S + su)), row sums ----
        {
            const int c01 = wsc * 8 + 2 * t;
            const float s0 = su_s[buf * 64 + c01], s1 = su_s[buf * 64 + c01 + 1];
            const int jw = wsc * 4 + t;
            #pragma unroll
            for (int mi = 0; mi < 2; mi++) {
                float p0 = __expf(accS[mi][0] + s0);
                float p1 = __expf(accS[mi][1] + s1);
                float p2 = __expf(accS[mi][2] + s0);
                float p3 = __expf(accS[mi][3] + s1);
                lsum[mi][0] += p0 + p1;
                lsum[mi][1] += p2 + p3;
                const int row = wsr * 32 + mi * 16 + g;
                Pw[row * 36 + jw]       = pk(p0, p1);
                Pw[(row + 8) * 36 + jw] = pk(p2, p3);
            }
        }
        __syncthreads();                 // P visible; all S-phase K reads done

        if (tt < NT - 1) {               // K(t+1) into single K buffer (overlaps PV)
            const int j1 = (tt + 1) * BN;
            #pragma unroll
            for (int p = 0; p < 8; p++) {
                int idx = tid + p * 512;
                int r = idx >> 6, c4 = idx & 63;
                cpa16(sb + A_KS + (r * 260 + c4 * 4) * 4,
                      &g_h[((size_t)(bbase + j1 + r)) * 512 + c4 * 4]);
            }
            CP_COMMIT();
        }

        // ---- O^T += K^T @ P^T : bf16, warp tile 64d x 16i, K=64 ----
        const uint32_t* Tb = Ktw + buf * 9216;
        #pragma unroll
        for (int kj = 0; kj < 4; kj++) {
            const int jw0 = kj * 8;
            uint32_t a[4][4];
            #pragma unroll
            for (int mi = 0; mi < 4; mi++) {
                const uint32_t* tp = Tb + (wor * 64 + mi * 16 + g) * 36 + jw0 + t;
                a[mi][0] = tp[0]; a[mi][1] = tp[8 * 36];
                a[mi][2] = tp[4]; a[mi][3] = tp[8 * 36 + 4];
            }
            #pragma unroll
            for (int ni = 0; ni < 2; ni++) {
                const uint32_t* pp = Pw + (woc * 16 + ni * 8 + g) * 36 + jw0 + t;
                uint32_t bf[2] = { pp[0], pp[4] };
                #pragma unroll
                for (int mi = 0; mi < 4; mi++) mma_bf16(accO[mi][ni], a[mi], bf);
            }
        }
    }

    // ---- row-sum reduce (8 wsc groups) ----
    #pragma unroll
    for (int mi = 0; mi < 2; mi++)
        #pragma unroll
        for (int rh = 0; rh < 2; rh++) {
            float v = lsum[mi][rh];
            v += __shfl_xor_sync(0xffffffffu, v, 1);
            v += __shfl_xor_sync(0xffffffffu, v, 2);
            if (t == 0) lsp[wsc * 64 + wsr * 32 + mi * 16 + rh * 8 + g] = v;
        }
    __syncthreads();
    if (tid < 64) {
        float s = 0.f;
        #pragma unroll
        for (int k = 0; k < 8; k++) s += lsp[k * 64 + tid];
        inv_s[tid] = 1.f / s;
    }
    __syncthreads();

    // ---- normalize, tf32-round, transpose via shfl, store to g_h attn-half ----
    const bool even = ((g & 1) == 0);
    #pragma unroll
    for (int mi = 0; mi < 4; mi++)
        #pragma unroll
        for (int ni = 0; ni < 2; ni++) {
            const int iA = woc * 16 + ni * 8 + 2 * t;
            const float invA = inv_s[iA], invB = inv_s[iA + 1];
            float c0 = f2tf(accO[mi][ni][0] * invA), c1 = f2tf(accO[mi][ni][1] * invB);
            float c2 = f2tf(accO[mi][ni][2] * invA), c3 = f2tf(accO[mi][ni][3] * invB);
            float v0 = __shfl_xor_sync(0xffffffffu, c0, 4);
            float v1 = __shfl_xor_sync(0xffffffffu, c1, 4);
            float v2 = __shfl_xor_sync(0xffffffffu, c2, 4);
            float v3 = __shfl_xor_sync(0xffffffffu, c3, 4);
            float* rowA = g_h + ((size_t)(bbase + q0 + iA)) * 512 + 256;
            float* rowB = rowA + 512;
            if (even) {
                const int d2 = (wor * 32 + mi * 8 + (g >> 1)) * 2;
                *(float2*)(rowA + d2) = make_float2(c0, v0);
                *(float2*)(rowB + d2) = make_float2(c1, v1);
            } else {
                const int d2 = (wor * 32 + mi * 8 + ((g + 7) >> 1)) * 2;
                *(float2*)(rowA + d2) = make_float2(v2, c2);
                *(float2*)(rowB + d2) = make_float2(v3, c3);
            }
        }
}

// ===========================================================================
// MLP tf32 (unchanged from R7): streamed H+W chunks, grid (256, 2), 256 thr.
// ===========================================================================
#define M_HS 0          // [2][64][36] f32
#define M_WS 18432      // [2][384][36] f32
#define M_END 129024

__global__ __launch_bounds__(256, 1)
void mlp_kernel(const float* __restrict__ x,
                const float* __restrict__ b1, const float* __restrict__ b2,
                const float* __restrict__ b3, float* __restrict__ out)
{
    extern __shared__ char smem[];
    const uint32_t sb = smem_u32(smem);
    const uint32_t* Hw = (const uint32_t*)(smem + M_HS);
    const uint32_t* Ww = (const uint32_t*)(smem + M_WS);

    const int tid = threadIdx.x, w = tid >> 5, lane = tid & 31;
    const int g = lane >> 2, t = lane & 3;
    const int wr = w & 1, wc = w >> 1;
    const int row0 = blockIdx.x * 64, n0 = blockIdx.y * 128;

    #pragma unroll
    for (int p = 0; p < 2; p++) {
        int idx = tid + p * 256;
        int r = idx >> 3, c = idx & 7;
        cpa16(sb + M_HS + (r * 36 + c * 4) * 4,
              &g_h[((size_t)(row0 + r)) * 512 + c * 4]);
    }
    #pragma unroll
    for (int p = 0; p < 12; p++) {
        int idx = tid + p * 256;
        int m = idx >> 10, rem = idx & 1023;
        int n = rem >> 3, c = rem & 7;
        cpa16(sb + M_WS + ((m * 128 + n) * 36 + c * 4) * 4,
              &g_wtf[((size_t)m * 256 + n0 + n) * 512 + c * 4]);
    }
    CP_COMMIT();

    float acc[3][2][4][4];
    #pragma unroll
    for (int m = 0; m < 3; m++)
        #pragma unroll
        for (int mi = 0; mi < 2; mi++)
            #pragma unroll
            for (int ni = 0; ni < 4; ni++)
                #pragma unroll
                for (int q = 0; q < 4; q++) acc[m][mi][ni][q] = 0.f;

    for (int s = 0; s < 16; s++) {
        CP_WAIT0();
        __syncthreads();
        const int buf = s & 1;

        if (s < 15) {
            const int nb = (s + 1) & 1, k1 = (s + 1) * 32;
            #pragma unroll
            for (int p = 0; p < 2; p++) {
                int idx = tid + p * 256;
                int r = idx >> 3, c = idx & 7;
                cpa16(sb + M_HS + nb * 9216 + (r * 36 + c * 4) * 4,
                      &g_h[((size_t)(row0 + r)) * 512 + k1 + c * 4]);
            }
            #pragma unroll
            for (int p = 0; p < 12; p++) {
                int idx = tid + p * 256;
                int m = idx >> 10, rem = idx & 1023;
                int n = rem >> 3, c = rem & 7;
                cpa16(sb + M_WS + nb * 55296 + ((m * 128 + n) * 36 + c * 4) * 4,
                      &g_wtf[((size_t)m * 256 + n0 + n) * 512 + k1 + c * 4]);
            }
            CP_COMMIT();
        }

        const uint32_t* Hb = Hw + buf * 2304;
        const uint32_t* Wb = Ww + buf * 13824;
        #pragma unroll
        for (int ks = 0; ks < 4; ks++) {
            uint32_t a[2][4];
            #pragma unroll
            for (int mi = 0; mi < 2; mi++) {
                const uint32_t* hp = Hb + (wr * 32 + mi * 16 + g) * 36 + ks * 8 + t;
                a[mi][0] = hp[0]; a[mi][1] = hp[8 * 36];
                a[mi][2] = hp[4]; a[mi][3] = hp[8 * 36 + 4];
            }
            #pragma unroll
            for (int m = 0; m < 3; m++)
                #pragma unroll
                for (int ni = 0; ni < 4; ni++) {
                    const uint32_t* wp2 = Wb + (m * 128 + wc * 32 + ni * 8 + g) * 36 + ks * 8 + t;
                    uint32_t bf[2] = { wp2[0], wp2[4] };
                    mma_tf32(acc[m][0][ni], a[0], bf);
                    mma_tf32(acc[m][1][ni], a[1], bf);
                }
        }
    }

    #pragma unroll
    for (int mi = 0; mi < 2; mi++)
        #pragma unroll
        for (int ni = 0; ni < 4; ni++) {
            const int rloc = wr * 32 + mi * 16 + g;
            const int cc = n0 + wc * 32 + ni * 8 + 2 * t;
            const float2 bb1 = *(const float2*)(b1 + cc);
            const float2 bb2 = *(const float2*)(b2 + cc);
            const float2 bb3 = *(const float2*)(b3 + cc);
            #pragma unroll
            for (int h = 0; h < 2; h++) {
                const int rl = rloc + h * 8, i0 = h * 2;
                float z0 = tanhf(acc[0][mi][ni][i0]     + bb1.x);
                float z1 = tanhf(acc[0][mi][ni][i0 + 1] + bb1.y);
                float r0 = 1.f / (1.f + __expf(-(acc[1][mi][ni][i0]     + bb2.x)));
                float r1 = 1.f / (1.f + __expf(-(acc[1][mi][ni][i0 + 1] + bb2.y)));
                float f0 = 1.f / (1.f + __expf(-(acc[2][mi][ni][i0]     + bb3.x)));
                float f1 = 1.f / (1.f + __expf(-(acc[2][mi][ni][i0 + 1] + bb3.y)));
                const float2 xv = *(const float2*)(x + (size_t)(row0 + rl) * DD + cc);
                float2 o = make_float2(r0 * xv.x + f0 * z0, r1 * xv.y + f1 * z1);
                *(float2*)(out + (size_t)(row0 + rl) * DD + cc) = o;
            }
        }
}

// ===========================================================================
extern "C" void kernel_launch(void* const* d_in, const int* in_sizes, int n_in,
                              void* d_out, int out_size)
{
    const float* x   = (const float*)d_in[0];
    const float* wia = (const float*)d_in[1];
    const float* w1  = (const float*)d_in[2];
    const float* w2  = (const float*)d_in[3];
    const float* w3  = (const float*)d_in[4];
    const float* b1  = (const float*)d_in[5];
    const float* b2  = (const float*)d_in[6];
    const float* b3  = (const float*)d_in[7];
    float* out = (float*)d_out;

    cudaFuncSetAttribute(attn_kernel, cudaFuncAttributeMaxDynamicSharedMemorySize, A_END);
    cudaFuncSetAttribute(mlp_kernel,  cudaFuncAttributeMaxDynamicSharedMemorySize, M_END);

    prep_su  <<<LL * BB / 8, 256>>>(x, wia);
    prep_pack<<<BB * 128, 256>>>(x, wia);
    prep_w   <<<96, 256>>>(w1, w2, w3);
    attn_kernel<<<dim3(LL / BM, BB), 512, A_END>>>();
    mlp_kernel <<<dim3(BB * LL / 64, 2), 256, M_END>>>(x, b1, b2, b3, out);
}

// round 10
// speedup vs baseline: 1.1791x; 1.1791x over previous
#include <cuda_runtime.h>
#include <cstdint>

#define BB 8
#define LL 2048
#define DD 256
#define BM 64
#define BN 64
#define NT (LL / BN)

// ---- global scratch (allocation-free device arrays) ----
__device__ float    g_yf[(size_t)BB * LL * DD];     // tf32(x*wp)
__device__ float    g_h [(size_t)BB * LL * 512];    // [tf32(x) | tf32(attn)]
__device__ uint32_t g_xT[(size_t)BB * 256 * 1024];  // x^T bf16 j-pairs
__device__ float    g_su[(size_t)BB * LL];
__device__ float    g_wtf[3 * 256 * 512];           // W^T tf32 [m][n][k]

// ---- helpers ----
__device__ __forceinline__ uint32_t smem_u32(const void* p) {
    uint32_t a;
    asm("{ .reg .u64 t; cvta.to.shared.u64 t, %1; cvt.u32.u64 %0, t; }" : "=r"(a) : "l"(p));
    return a;
}
__device__ __forceinline__ uint32_t pk(float lo, float hi) {
    uint32_t r; asm("cvt.rn.bf16x2.f32 %0, %1, %2;" : "=r"(r) : "f"(hi), "f"(lo)); return r;
}
__device__ __forceinline__ float f2tf(float f) {
    uint32_t u; asm("cvt.rna.tf32.f32 %0, %1;" : "=r"(u) : "f"(f)); return __uint_as_float(u);
}
__device__ __forceinline__ void cpa16(uint32_t dst, const void* src) {
    asm volatile("cp.async.ca.shared.global [%0], [%1], 16;" :: "r"(dst), "l"(src));
}
#define CP_COMMIT() asm volatile("cp.async.commit_group;")
#define CP_WAIT0()  asm volatile("cp.async.wait_group 0;")

__device__ __forceinline__ void mma_bf16(float* c, const uint32_t* a, const uint32_t* b) {
    asm volatile("mma.sync.aligned.m16n8k16.row.col.f32.bf16.bf16.f32 "
        "{%0,%1,%2,%3}, {%4,%5,%6,%7}, {%8,%9}, {%0,%1,%2,%3};"
        : "+f"(c[0]), "+f"(c[1]), "+f"(c[2]), "+f"(c[3])
        : "r"(a[0]), "r"(a[1]), "r"(a[2]), "r"(a[3]), "r"(b[0]), "r"(b[1]));
}
__device__ __forceinline__ void mma_tf32(float* c, const uint32_t* a, const uint32_t* b) {
    asm volatile("mma.sync.aligned.m16n8k8.row.col.f32.tf32.tf32.f32 "
        "{%0,%1,%2,%3}, {%4,%5,%6,%7}, {%8,%9}, {%0,%1,%2,%3};"
        : "+f"(c[0]), "+f"(c[1]), "+f"(c[2]), "+f"(c[3])
        : "r"(a[0]), "r"(a[1]), "r"(a[2]), "r"(a[3]), "r"(b[0]), "r"(b[1]));
}

// ===========================================================================
// prep kernels
// ===========================================================================
__global__ void prep_su(const float* __restrict__ x, const float* __restrict__ w_itr) {
    int row = blockIdx.x * 8 + (threadIdx.x >> 5);
    int lane = threadIdx.x & 31;
    const float* xr = x + (size_t)row * DD;
    float s = 0.f;
    #pragma unroll
    for (int k = 0; k < 8; k++) s += xr[lane + 32 * k] * w_itr[lane + 32 * k];
    #pragma unroll
    for (int off = 16; off > 0; off >>= 1) s += __shfl_xor_sync(0xffffffffu, s, off);
    if (lane == 0) g_su[row] = s;
}

__global__ void prep_pack(const float* __restrict__ x, const float* __restrict__ w_itr) {
    __shared__ float tl[64][65];
    int blk = blockIdx.x;                      // b*128 + jt*4 + dt
    int b = blk >> 7, rem = blk & 127, jt = rem >> 2, dt = rem & 3;
    int j0 = jt * 64, d0 = dt * 64;
    const float* xb = x + ((size_t)b * LL + j0) * DD + d0;
    int tid = threadIdx.x;
    #pragma unroll
    for (int p = 0; p < 4; p++) {
        int idx = tid + p * 256;
        int r = idx >> 4, c4 = idx & 15;
        float4 v = *(const float4*)(xb + (size_t)r * DD + c4 * 4);
        tl[r][c4 * 4 + 0] = v.x; tl[r][c4 * 4 + 1] = v.y;
        tl[r][c4 * 4 + 2] = v.z; tl[r][c4 * 4 + 3] = v.w;
    }
    __syncthreads();
    const float* wp = w_itr + 2 * DD;
    #pragma unroll
    for (int p = 0; p < 4; p++) {
        int idx = tid + p * 256;
        int r = idx >> 4, c4 = idx & 15;
        float a0 = tl[r][c4 * 4 + 0], a1 = tl[r][c4 * 4 + 1];
        float a2 = tl[r][c4 * 4 + 2], a3 = tl[r][c4 * 4 + 3];
        float4 y, h;
        y.x = f2tf(a0 * wp[d0 + c4 * 4 + 0]); y.y = f2tf(a1 * wp[d0 + c4 * 4 + 1]);
        y.z = f2tf(a2 * wp[d0 + c4 * 4 + 2]); y.w = f2tf(a3 * wp[d0 + c4 * 4 + 3]);
        h.x = f2tf(a0); h.y = f2tf(a1); h.z = f2tf(a2); h.w = f2tf(a3);
        *(float4*)(g_yf + ((size_t)b * LL + j0 + r) * DD + d0 + c4 * 4) = y;
        *(float4*)(g_h  + ((size_t)b * LL + j0 + r) * 512 + d0 + c4 * 4) = h;
    }
    #pragma unroll
    for (int p = 0; p < 8; p++) {
        int idx = tid + p * 256;
        int dl = idx >> 5, jw = idx & 31;
        g_xT[((size_t)b * 256 + d0 + dl) * 1024 + (j0 >> 1) + jw] =
            pk(tl[2 * jw][dl], tl[2 * jw + 1][dl]);
    }
}

__global__ void prep_w(const float* __restrict__ w1, const float* __restrict__ w2,
                       const float* __restrict__ w3) {
    __shared__ float tl[64][65];
    int blk = blockIdx.x;                        // m*32 + kt*4 + nt
    int m = blk >> 5, rem = blk & 31, kt = rem >> 2, nt = rem & 3;
    int k0 = kt * 64, n0 = nt * 64;
    const float* W = (m == 0) ? w1 : (m == 1) ? w2 : w3;
    int tid = threadIdx.x;
    #pragma unroll
    for (int p = 0; p < 4; p++) {
        int idx = tid + p * 256;
        int r = idx >> 4, c4 = idx & 15;
        float4 v = *(const float4*)(W + (size_t)(k0 + r) * DD + n0 + c4 * 4);
        tl[r][c4 * 4 + 0] = v.x; tl[r][c4 * 4 + 1] = v.y;
        tl[r][c4 * 4 + 2] = v.z; tl[r][c4 * 4 + 3] = v.w;
    }
    __syncthreads();
    #pragma unroll
    for (int p = 0; p < 4; p++) {
        int idx = tid + p * 256;
        int nl = idx >> 4, kc4 = idx & 15;
        float4 o;
        o.x = f2tf(tl[kc4 * 4 + 0][nl]); o.y = f2tf(tl[kc4 * 4 + 1][nl]);
        o.z = f2tf(tl[kc4 * 4 + 2][nl]); o.w = f2tf(tl[kc4 * 4 + 3][nl]);
        *(float4*)(g_wtf + ((size_t)m * 256 + n0 + nl) * 512 + k0 + kc4 * 4) = o;
    }
}

// ===========================================================================
// attention, 256 thr / 8 warps (R7 tiling), K tile cp.async overlapped w/ PV.
// S grid 2x4 (warp 32x16), PV grid 4x2 (warp 64d x 32i).
// ===========================================================================
#define A_SU  0        // [2][64] f32
#define A_INV 512
#define A_LSP 768
#define A_YS  1792     // [64][260] f32
#define A_KS  68352    // [64][260] f32 (single buffer, cp.async)
#define A_KT  134912   // [2][256][36] u32
#define A_PS  208640   // [64][36] u32
#define A_END 217856

__global__ __launch_bounds__(256, 1) void attn_kernel() {
    extern __shared__ char smem[];
    const uint32_t sb = smem_u32(smem);
    float* su_s  = (float*)(smem + A_SU);
    float* inv_s = (float*)(smem + A_INV);
    float* lsp   = (float*)(smem + A_LSP);
    const uint32_t* Ysw = (const uint32_t*)(smem + A_YS);
    const uint32_t* Ksw = (const uint32_t*)(smem + A_KS);
    const uint32_t* Ktw = (const uint32_t*)(smem + A_KT);
    uint32_t* Pw = (uint32_t*)(smem + A_PS);

    const int tid = threadIdx.x, w = tid >> 5, lane = tid & 31;
    const int g = lane >> 2, t = lane & 3;
    const int wsr = w & 1, wsc = w >> 1;      // S grid 2x4
    const int wor = w & 3, woc = w >> 2;      // PV grid 4x2
    const int b = blockIdx.y, q0 = blockIdx.x * BM;
    const int bbase = b * LL;

    // ---- preamble: cp.async Y, K(0), Kt(0), su(0) ----
    #pragma unroll
    for (int p = 0; p < 16; p++) {
        int idx = tid + p * 256;
        int r = idx >> 6, c4 = idx & 63;
        cpa16(sb + A_YS + (r * 260 + c4 * 4) * 4,
              &g_yf[((size_t)(bbase + q0 + r)) * DD + c4 * 4]);
    }
    #pragma unroll
    for (int p = 0; p < 16; p++) {
        int idx = tid + p * 256;
        int r = idx >> 6, c4 = idx & 63;
        cpa16(sb + A_KS + (r * 260 + c4 * 4) * 4,
              &g_h[((size_t)(bbase + r)) * 512 + c4 * 4]);
    }
    #pragma unroll
    for (int p = 0; p < 8; p++) {
        int idx = tid + p * 256;
        int d = idx >> 3, c = idx & 7;
        cpa16(sb + A_KT + (d * 36 + c * 4) * 4,
              &g_xT[((size_t)(b * 256 + d)) * 1024 + c * 4]);
    }
    if (tid < 16) cpa16(sb + A_SU + tid * 16, &g_su[bbase + tid * 4]);
    CP_COMMIT();

    float accO[4][4][4];
    #pragma unroll
    for (int mi = 0; mi < 4; mi++)
        #pragma unroll
        for (int ni = 0; ni < 4; ni++)
            #pragma unroll
            for (int q = 0; q < 4; q++) accO[mi][ni][q] = 0.f;
    float lsum[2][2] = {{0.f, 0.f}, {0.f, 0.f}};

    for (int tt = 0; tt < NT; tt++) {
        CP_WAIT0();
        __syncthreads();                 // Y/K(tt)/Kt(tt)/su(tt) ready; prior PV done
        const int buf = tt & 1;

        if (tt < NT - 1) {               // prefetch Kt(t+1)/su(t+1)
            const int nb = (tt + 1) & 1, j1 = (tt + 1) * BN;
            #pragma unroll
            for (int p = 0; p < 8; p++) {
                int idx = tid + p * 256;
                int d = idx >> 3, c = idx & 7;
                cpa16(sb + A_KT + nb * 36864 + (d * 36 + c * 4) * 4,
                      &g_xT[((size_t)(b * 256 + d)) * 1024 + (j1 >> 1) + c * 4]);
            }
            if (tid < 16) cpa16(sb + A_SU + nb * 256 + tid * 16, &g_su[bbase + j1 + tid * 4]);
            CP_COMMIT();
        }

        // ---- S = Y @ K^T : tf32, warp tile 32x16, K=256 ----
        float accS[2][2][4];
        #pragma unroll
        for (int mi = 0; mi < 2; mi++)
            #pragma unroll
            for (int ni = 0; ni < 2; ni++)
                #pragma unroll
                for (int q = 0; q < 4; q++) accS[mi][ni][q] = 0.f;
        #pragma unroll 8
        for (int ks = 0; ks < 32; ks++) {
            const int d0 = ks * 8;
            uint32_t a[2][4], bf[2][2];
            #pragma unroll
            for (int mi = 0; mi < 2; mi++) {
                const uint32_t* yp = Ysw + (wsr * 32 + mi * 16 + g) * 260 + d0 + t;
                a[mi][0] = yp[0]; a[mi][1] = yp[8 * 260];
                a[mi][2] = yp[4]; a[mi][3] = yp[8 * 260 + 4];
            }
            #pragma unroll
            for (int ni = 0; ni < 2; ni++) {
                const uint32_t* kp = Ksw + (wsc * 16 + ni * 8 + g) * 260 + d0 + t;
                bf[ni][0] = kp[0]; bf[ni][1] = kp[4];
            }
            #pragma unroll
            for (int mi = 0; mi < 2; mi++)
                #pragma unroll
                for (int ni = 0; ni < 2; ni++) mma_tf32(accS[mi][ni], a[mi], bf[ni]);
        }

        // ---- epilogue: P = bf16(exp(S + su)), row sums ----
        #pragma unroll
        for (int mi = 0; mi < 2; mi++)
            #pragma unroll
            for (int ni = 0; ni < 2; ni++) {
                const int c01 = wsc * 16 + ni * 8 + 2 * t;
                const float s0 = su_s[buf * 64 + c01], s1 = su_s[buf * 64 + c01 + 1];
                float p0 = __expf(accS[mi][ni][0] + s0);
                float p1 = __expf(accS[mi][ni][1] + s1);
                float p2 = __expf(accS[mi][ni][2] + s0);
                float p3 = __expf(accS[mi][ni][3] + s1);
                lsum[mi][0] += p0 + p1;
                lsum[mi][1] += p2 + p3;
                const int row = wsr * 32 + mi * 16 + g;
                const int jw = wsc * 8 + ni * 4 + t;
                Pw[row * 36 + jw]       = pk(p0, p1);
                Pw[(row + 8) * 36 + jw] = pk(p2, p3);
            }
        __syncthreads();                 // P visible; S-phase K reads done

        if (tt < NT - 1) {               // K(t+1) cp.async — overlaps PV phase
            const int j1 = (tt + 1) * BN;
            #pragma unroll
            for (int p = 0; p < 16; p++) {
                int idx = tid + p * 256;
                int r = idx >> 6, c4 = idx & 63;
                cpa16(sb + A_KS + (r * 260 + c4 * 4) * 4,
                      &g_h[((size_t)(bbase + j1 + r)) * 512 + c4 * 4]);
            }
            CP_COMMIT();
        }

        // ---- O^T += K^T @ P^T : bf16, warp tile 64d x 32i, K=64 ----
        const uint32_t* Tb = Ktw + buf * 9216;
        #pragma unroll
        for (int kj = 0; kj < 4; kj++) {
            const int jw0 = kj * 8;
            uint32_t a[4][4];
            #pragma unroll
            for (int mi = 0; mi < 4; mi++) {
                const uint32_t* tp = Tb + (wor * 64 + mi * 16 + g) * 36 + jw0 + t;
                a[mi][0] = tp[0]; a[mi][1] = tp[8 * 36];
                a[mi][2] = tp[4]; a[mi][3] = tp[8 * 36 + 4];
            }
            #pragma unroll
            for (int ni = 0; ni < 4; ni++) {
                const uint32_t* pp = Pw + (woc * 32 + ni * 8 + g) * 36 + jw0 + t;
                uint32_t bf[2] = { pp[0], pp[4] };
                #pragma unroll
                for (int mi = 0; mi < 4; mi++) mma_bf16(accO[mi][ni], a[mi], bf);
            }
        }
    }

    // ---- row-sum reduce ----
    #pragma unroll
    for (int mi = 0; mi < 2; mi++)
        #pragma unroll
        for (int rh = 0; rh < 2; rh++) {
            float v = lsum[mi][rh];
            v += __shfl_xor_sync(0xffffffffu, v, 1);
            v += __shfl_xor_sync(0xffffffffu, v, 2);
            if (t == 0) lsp[wsc * 64 + wsr * 32 + mi * 16 + rh * 8 + g] = v;
        }
    __syncthreads();
    if (tid < 64)
        inv_s[tid] = 1.f / (lsp[tid] + lsp[64 + tid] + lsp[128 + tid] + lsp[192 + tid]);
    __syncthreads();

    // ---- normalize, tf32-round, transpose via shfl, store to g_h attn-half ----
    const bool even = ((g & 1) == 0);
    #pragma unroll
    for (int mi = 0; mi < 4; mi++)
        #pragma unroll
        for (int ni = 0; ni < 4; ni++) {
            const int iA = woc * 32 + ni * 8 + 2 * t;
            const float invA = inv_s[iA], invB = inv_s[iA + 1];
            float c0 = f2tf(accO[mi][ni][0] * invA), c1 = f2tf(accO[mi][ni][1] * invB);
            float c2 = f2tf(accO[mi][ni][2] * invA), c3 = f2tf(accO[mi][ni][3] * invB);
            float v0 = __shfl_xor_sync(0xffffffffu, c0, 4);
            float v1 = __shfl_xor_sync(0xffffffffu, c1, 4);
            float v2 = __shfl_xor_sync(0xffffffffu, c2, 4);
            float v3 = __shfl_xor_sync(0xffffffffu, c3, 4);
            float* rowA = g_h + ((size_t)(bbase + q0 + iA)) * 512 + 256;
            float* rowB = rowA + 512;
            if (even) {
                const int d2 = (wor * 32 + mi * 8 + (g >> 1)) * 2;
                *(float2*)(rowA + d2) = make_float2(c0, v0);
                *(float2*)(rowB + d2) = make_float2(c1, v1);
            } else {
                const int d2 = (wor * 32 + mi * 8 + ((g + 7) >> 1)) * 2;
                *(float2*)(rowA + d2) = make_float2(v2, c2);
                *(float2*)(rowB + d2) = make_float2(v3, c3);
            }
        }
}

// ===========================================================================
// MLP tf32: grid (128, 4), 256 thr. 128 rows x 64 cols per CTA (halves
// W L2 traffic vs R7). H chunks [128][36] + W chunks [192][36], dbl-buffered.
// Warp grid 4m x 2n: warp tile 32 rows x 32 cols (x3 gates).
// ===========================================================================
#define M_HS 0          // [2][128][36] f32 = 36864
#define M_WS 36864      // [2][192][36] f32 = 55296
#define M_END 92160

__global__ __launch_bounds__(256, 1)
void mlp_kernel(const float* __restrict__ x,
                const float* __restrict__ b1, const float* __restrict__ b2,
                const float* __restrict__ b3, float* __restrict__ out)
{
    extern __shared__ char smem[];
    const uint32_t sb = smem_u32(smem);
    const uint32_t* Hw = (const uint32_t*)(smem + M_HS);
    const uint32_t* Ww = (const uint32_t*)(smem + M_WS);

    const int tid = threadIdx.x, w = tid >> 5, lane = tid & 31;
    const int g = lane >> 2, t = lane & 3;
    const int mw = w >> 1, nw = w & 1;        // 4 m-warps x 2 n-warps
    const int row0 = blockIdx.x * 128, n0 = blockIdx.y * 64;

    // chunk 0: H k=0..31, W k=0..31
    #pragma unroll
    for (int p = 0; p < 4; p++) {
        int idx = tid + p * 256;
        int r = idx >> 3, c = idx & 7;
        cpa16(sb + M_HS + (r * 36 + c * 4) * 4,
              &g_h[((size_t)(row0 + r)) * 512 + c * 4]);
    }
    #pragma unroll
    for (int p = 0; p < 6; p++) {
        int idx = tid + p * 256;
        int m = idx >> 9, rem = idx & 511;
        int n = rem >> 3, c = rem & 7;
        cpa16(sb + M_WS + ((m * 64 + n) * 36 + c * 4) * 4,
              &g_wtf[((size_t)m * 256 + n0 + n) * 512 + c * 4]);
    }
    CP_COMMIT();

    float acc[3][2][4][4];
    #pragma unroll
    for (int m = 0; m < 3; m++)
        #pragma unroll
        for (int mi = 0; mi < 2; mi++)
            #pragma unroll
            for (int ni = 0; ni < 4; ni++)
                #pragma unroll
                for (int q = 0; q < 4; q++) acc[m][mi][ni][q] = 0.f;

    for (int s = 0; s < 16; s++) {
        CP_WAIT0();
        __syncthreads();
        const int buf = s & 1;

        if (s < 15) {
            const int nb = (s + 1) & 1, k1 = (s + 1) * 32;
            #pragma unroll
            for (int p = 0; p < 4; p++) {
                int idx = tid + p * 256;
                int r = idx >> 3, c = idx & 7;
                cpa16(sb + M_HS + nb * 18432 + (r * 36 + c * 4) * 4,
                      &g_h[((size_t)(row0 + r)) * 512 + k1 + c * 4]);
            }
            #pragma unroll
            for (int p = 0; p < 6; p++) {
                int idx = tid + p * 256;
                int m = idx >> 9, rem = idx & 511;
                int n = rem >> 3, c = rem & 7;
                cpa16(sb + M_WS + nb * 27648 + ((m * 64 + n) * 36 + c * 4) * 4,
                      &g_wtf[((size_t)m * 256 + n0 + n) * 512 + k1 + c * 4]);
            }
            CP_COMMIT();
        }

        const uint32_t* Hb = Hw + buf * 4608;
        const uint32_t* Wb = Ww + buf * 6912;
        #pragma unroll
        for (int ks = 0; ks < 4; ks++) {
            uint32_t a[2][4];
            #pragma unroll
            for (int mi = 0; mi < 2; mi++) {
                const uint32_t* hp = Hb + (mw * 32 + mi * 16 + g) * 36 + ks * 8 + t;
                a[mi][0] = hp[0]; a[mi][1] = hp[8 * 36];
                a[mi][2] = hp[4]; a[mi][3] = hp[8 * 36 + 4];
            }
            #pragma unroll
            for (int m = 0; m < 3; m++)
                #pragma unroll
                for (int ni = 0; ni < 4; ni++) {
                    const uint32_t* wp2 = Wb + (m * 64 + nw * 32 + ni * 8 + g) * 36 + ks * 8 + t;
                    uint32_t bf[2] = { wp2[0], wp2[4] };
                    mma_tf32(acc[m][0][ni], a[0], bf);
                    mma_tf32(acc[m][1][ni], a[1], bf);
                }
        }
    }

    // fused epilogue
    #pragma unroll
    for (int mi = 0; mi < 2; mi++)
        #pragma unroll
        for (int ni = 0; ni < 4; ni++) {
            const int rloc = mw * 32 + mi * 16 + g;
            const int cc = n0 + nw * 32 + ni * 8 + 2 * t;
            const float2 bb1 = *(const float2*)(b1 + cc);
            const float2 bb2 = *(const float2*)(b2 + cc);
            const float2 bb3 = *(const float2*)(b3 + cc);
            #pragma unroll
            for (int h = 0; h < 2; h++) {
                const int rl = rloc + h * 8, i0 = h * 2;
                float z0 = tanhf(acc[0][mi][ni][i0]     + bb1.x);
                float z1 = tanhf(acc[0][mi][ni][i0 + 1] + bb1.y);
                float r0 = 1.f / (1.f + __expf(-(acc[1][mi][ni][i0]     + bb2.x)));
                float r1 = 1.f / (1.f + __expf(-(acc[1][mi][ni][i0 + 1] + bb2.y)));
                float f0 = 1.f / (1.f + __expf(-(acc[2][mi][ni][i0]     + bb3.x)));
                float f1 = 1.f / (1.f + __expf(-(acc[2][mi][ni][i0 + 1] + bb3.y)));
                const float2 xv = *(const float2*)(x + (size_t)(row0 + rl) * DD + cc);
                float2 o = make_float2(r0 * xv.x + f0 * z0, r1 * xv.y + f1 * z1);
                *(float2*)(out + (size_t)(row0 + rl) * DD + cc) = o;
            }
        }
}

// ===========================================================================
extern "C" void kernel_launch(void* const* d_in, const int* in_sizes, int n_in,
                              void* d_out, int out_size)
{
    const float* x   = (const float*)d_in[0];
    const float* wia = (const float*)d_in[1];
    const float* w1  = (const float*)d_in[2];
    const float* w2  = (const float*)d_in[3];
    const float* w3  = (const float*)d_in[4];
    const float* b1  = (const float*)d_in[5];
    const float* b2  = (const float*)d_in[6];
    const float* b3  = (const float*)d_in[7];
    float* out = (float*)d_out;

    cudaFuncSetAttribute(attn_kernel, cudaFuncAttributeMaxDynamicSharedMemorySize, A_END);
    cudaFuncSetAttribute(mlp_kernel,  cudaFuncAttributeMaxDynamicSharedMemorySize, M_END);

    prep_su  <<<LL * BB / 8, 256>>>(x, wia);
    prep_pack<<<BB * 128, 256>>>(x, wia);
    prep_w   <<<96, 256>>>(w1, w2, w3);
    attn_kernel<<<dim3(LL / BM, BB), 256, A_END>>>();
    mlp_kernel <<<dim3(BB * LL / 128, 4), 256, M_END>>>(x, b1, b2, b3, out);
}

// round 12
// speedup vs baseline: 1.2050x; 1.0220x over previous
#include <cuda_runtime.h>
#include <cstdint>

#define BB 8
#define LL 2048
#define DD 256
#define BM 64
#define BN 64
#define NT (LL / BN)

// ---- global scratch (allocation-free device arrays) ----
__device__ float    g_yf[(size_t)BB * LL * DD];     // tf32(x*wp)
__device__ float    g_h [(size_t)BB * LL * 512];    // [tf32(x) | tf32(attn)]
__device__ uint32_t g_xT[(size_t)BB * 256 * 1024];  // x^T bf16 j-pairs
__device__ float    g_su[(size_t)BB * LL];
__device__ float    g_wtf[3 * 256 * 512];           // W^T tf32 [m][n][k]

// ---- helpers ----
__device__ __forceinline__ uint32_t smem_u32(const void* p) {
    uint32_t a;
    asm("{ .reg .u64 t; cvta.to.shared.u64 t, %1; cvt.u32.u64 %0, t; }" : "=r"(a) : "l"(p));
    return a;
}
__device__ __forceinline__ uint32_t pk(float lo, float hi) {
    uint32_t r; asm("cvt.rn.bf16x2.f32 %0, %1, %2;" : "=r"(r) : "f"(hi), "f"(lo)); return r;
}
__device__ __forceinline__ float f2tf(float f) {
    uint32_t u; asm("cvt.rna.tf32.f32 %0, %1;" : "=r"(u) : "f"(f)); return __uint_as_float(u);
}
__device__ __forceinline__ void cpa16(uint32_t dst, const void* src) {
    asm volatile("cp.async.ca.shared.global [%0], [%1], 16;" :: "r"(dst), "l"(src));
}
#define CP_COMMIT() asm volatile("cp.async.commit_group;")
#define CP_WAIT0()  asm volatile("cp.async.wait_group 0;")

__device__ __forceinline__ void ldsm4(uint32_t* r, uint32_t addr) {
    asm volatile("ldmatrix.sync.aligned.m8n8.x4.shared.b16 {%0,%1,%2,%3}, [%4];"
        : "=r"(r[0]), "=r"(r[1]), "=r"(r[2]), "=r"(r[3]) : "r"(addr));
}
__device__ __forceinline__ void mma_bf16(float* c, const uint32_t* a, const uint32_t* b) {
    asm volatile("mma.sync.aligned.m16n8k16.row.col.f32.bf16.bf16.f32 "
        "{%0,%1,%2,%3}, {%4,%5,%6,%7}, {%8,%9}, {%0,%1,%2,%3};"
        : "+f"(c[0]), "+f"(c[1]), "+f"(c[2]), "+f"(c[3])
        : "r"(a[0]), "r"(a[1]), "r"(a[2]), "r"(a[3]), "r"(b[0]), "r"(b[1]));
}
__device__ __forceinline__ void mma_tf32(float* c, const uint32_t* a, const uint32_t* b) {
    asm volatile("mma.sync.aligned.m16n8k8.row.col.f32.tf32.tf32.f32 "
        "{%0,%1,%2,%3}, {%4,%5,%6,%7}, {%8,%9}, {%0,%1,%2,%3};"
        : "+f"(c[0]), "+f"(c[1]), "+f"(c[2]), "+f"(c[3])
        : "r"(a[0]), "r"(a[1]), "r"(a[2]), "r"(a[3]), "r"(b[0]), "r"(b[1]));
}

// ===========================================================================
// prep kernels (unchanged)
// ===========================================================================
__global__ void prep_su(const float* __restrict__ x, const float* __restrict__ w_itr) {
    int row = blockIdx.x * 8 + (threadIdx.x >> 5);
    int lane = threadIdx.x & 31;
    const float* xr = x + (size_t)row * DD;
    float s = 0.f;
    #pragma unroll
    for (int k = 0; k < 8; k++) s += xr[lane + 32 * k] * w_itr[lane + 32 * k];
    #pragma unroll
    for (int off = 16; off > 0; off >>= 1) s += __shfl_xor_sync(0xffffffffu, s, off);
    if (lane == 0) g_su[row] = s;
}

__global__ void prep_pack(const float* __restrict__ x, const float* __restrict__ w_itr) {
    __shared__ float tl[64][65];
    int blk = blockIdx.x;                      // b*128 + jt*4 + dt
    int b = blk >> 7, rem = blk & 127, jt = rem >> 2, dt = rem & 3;
    int j0 = jt * 64, d0 = dt * 64;
    const float* xb = x + ((size_t)b * LL + j0) * DD + d0;
    int tid = threadIdx.x;
    #pragma unroll
    for (int p = 0; p < 4; p++) {
        int idx = tid + p * 256;
        int r = idx >> 4, c4 = idx & 15;
        float4 v = *(const float4*)(xb + (size_t)r * DD + c4 * 4);
        tl[r][c4 * 4 + 0] = v.x; tl[r][c4 * 4 + 1] = v.y;
        tl[r][c4 * 4 + 2] = v.z; tl[r][c4 * 4 + 3] = v.w;
    }
    __syncthreads();
    const float* wp = w_itr + 2 * DD;
    #pragma unroll
    for (int p = 0; p < 4; p++) {
        int idx = tid + p * 256;
        int r = idx >> 4, c4 = idx & 15;
        float a0 = tl[r][c4 * 4 + 0], a1 = tl[r][c4 * 4 + 1];
        float a2 = tl[r][c4 * 4 + 2], a3 = tl[r][c4 * 4 + 3];
        float4 y, h;
        y.x = f2tf(a0 * wp[d0 + c4 * 4 + 0]); y.y = f2tf(a1 * wp[d0 + c4 * 4 + 1]);
        y.z = f2tf(a2 * wp[d0 + c4 * 4 + 2]); y.w = f2tf(a3 * wp[d0 + c4 * 4 + 3]);
        h.x = f2tf(a0); h.y = f2tf(a1); h.z = f2tf(a2); h.w = f2tf(a3);
        *(float4*)(g_yf + ((size_t)b * LL + j0 + r) * DD + d0 + c4 * 4) = y;
        *(float4*)(g_h  + ((size_t)b * LL + j0 + r) * 512 + d0 + c4 * 4) = h;
    }
    #pragma unroll
    for (int p = 0; p < 8; p++) {
        int idx = tid + p * 256;
        int dl = idx >> 5, jw = idx & 31;
        g_xT[((size_t)b * 256 + d0 + dl) * 1024 + (j0 >> 1) + jw] =
            pk(tl[2 * jw][dl], tl[2 * jw + 1][dl]);
    }
}

__global__ void prep_w(const float* __restrict__ w1, const float* __restrict__ w2,
                       const float* __restrict__ w3) {
    __shared__ float tl[64][65];
    int blk = blockIdx.x;                        // m*32 + kt*4 + nt
    int m = blk >> 5, rem = blk & 31, kt = rem >> 2, nt = rem & 3;
    int k0 = kt * 64, n0 = nt * 64;
    const float* W = (m == 0) ? w1 : (m == 1) ? w2 : w3;
    int tid = threadIdx.x;
    #pragma unroll
    for (int p = 0; p < 4; p++) {
        int idx = tid + p * 256;
        int r = idx >> 4, c4 = idx & 15;
        float4 v = *(const float4*)(W + (size_t)(k0 + r) * DD + n0 + c4 * 4);
        tl[r][c4 * 4 + 0] = v.x; tl[r][c4 * 4 + 1] = v.y;
        tl[r][c4 * 4 + 2] = v.z; tl[r][c4 * 4 + 3] = v.w;
    }
    __syncthreads();
    #pragma unroll
    for (int p = 0; p < 4; p++) {
        int idx = tid + p * 256;
        int nl = idx >> 4, kc4 = idx & 15;
        float4 o;
        o.x = f2tf(tl[kc4 * 4 + 0][nl]); o.y = f2tf(tl[kc4 * 4 + 1][nl]);
        o.z = f2tf(tl[kc4 * 4 + 2][nl]); o.w = f2tf(tl[kc4 * 4 + 3][nl]);
        *(float4*)(g_wtf + ((size_t)m * 256 + n0 + nl) * 512 + k0 + kc4 * 4) = o;
    }
}

// ===========================================================================
// attention, 256 thr / 8 warps. Same layout as R10; fragment loads via
// ldmatrix.x4 (tf32 frags through b16 tiles; bf16 frags native).
// ===========================================================================
#define A_SU  0        // [2][64] f32
#define A_INV 512
#define A_LSP 768
#define A_YS  1792     // [64][260] f32
#define A_KS  68352    // [64][260] f32 (single buffer, cp.async)
#define A_KT  134912   // [2][256][36] u32
#define A_PS  208640   // [64][36] u32
#define A_END 217856

__global__ __launch_bounds__(256, 1) void attn_kernel() {
    extern __shared__ char smem[];
    const uint32_t sb = smem_u32(smem);
    float* su_s  = (float*)(smem + A_SU);
    float* inv_s = (float*)(smem + A_INV);
    float* lsp   = (float*)(smem + A_LSP);
    uint32_t* Pw = (uint32_t*)(smem + A_PS);

    const int tid = threadIdx.x, w = tid >> 5, lane = tid & 31;
    const int g = lane >> 2, t = lane & 3;
    const int wsr = w & 1, wsc = w >> 1;      // S grid 2x4
    const int wor = w & 3, woc = w >> 2;      // PV grid 4x2
    const int b = blockIdx.y, q0 = blockIdx.x * BM;
    const int bbase = b * LL;

    // lane-derived ldmatrix row/col selectors
    const int l7  = lane & 7;
    const int l8h = (lane >> 3) & 1;
    const int l16 = lane >> 4;

    // S-phase bases: A from Y (x4: rows g/g+8, word t/t+4), B from K (x4: ni0+ni1)
    const uint32_t aY0 = sb + A_YS + (uint32_t)(((wsr * 32 + l7 + l8h * 8) * 260 + l16 * 4) * 4);
    const uint32_t aY1 = aY0 + 16 * 260 * 4;
    const uint32_t aKB = sb + A_KS + (uint32_t)(((wsc * 16 + l16 * 8 + l7) * 260 + l8h * 4) * 4);
    // PV bases: A from Kt, B from P
    const uint32_t aT0 = sb + A_KT + (uint32_t)(((wor * 64 + l7 + l8h * 8) * 36 + l16 * 4) * 4);
    const uint32_t aP0 = sb + A_PS + (uint32_t)(((woc * 32 + l16 * 8 + l7) * 36 + l8h * 4) * 4);

    // ---- preamble: cp.async Y, K(0), Kt(0), su(0) ----
    #pragma unroll
    for (int p = 0; p < 16; p++) {
        int idx = tid + p * 256;
        int r = idx >> 6, c4 = idx & 63;
        cpa16(sb + A_YS + (r * 260 + c4 * 4) * 4,
              &g_yf[((size_t)(bbase + q0 + r)) * DD + c4 * 4]);
    }
    #pragma unroll
    for (int p = 0; p < 16; p++) {
        int idx = tid + p * 256;
        int r = idx >> 6, c4 = idx & 63;
        cpa16(sb + A_KS + (r * 260 + c4 * 4) * 4,
              &g_h[((size_t)(bbase + r)) * 512 + c4 * 4]);
    }
    #pragma unroll
    for (int p = 0; p < 8; p++) {
        int idx = tid + p * 256;
        int d = idx >> 3, c = idx & 7;
        cpa16(sb + A_KT + (d * 36 + c * 4) * 4,
              &g_xT[((size_t)(b * 256 + d)) * 1024 + c * 4]);
    }
    if (tid < 16) cpa16(sb + A_SU + tid * 16, &g_su[bbase + tid * 4]);
    CP_COMMIT();

    float accO[4][4][4];
    #pragma unroll
    for (int mi = 0; mi < 4; mi++)
        #pragma unroll
        for (int ni = 0; ni < 4; ni++)
            #pragma unroll
            for (int q = 0; q < 4; q++) accO[mi][ni][q] = 0.f;
    float lsum[2][2] = {{0.f, 0.f}, {0.f, 0.f}};

    for (int tt = 0; tt < NT; tt++) {
        CP_WAIT0();
        __syncthreads();
        const int buf = tt & 1;

        if (tt < NT - 1) {               // prefetch Kt(t+1)/su(t+1)
            const int nb = (tt + 1) & 1, j1 = (tt + 1) * BN;
            #pragma unroll
            for (int p = 0; p < 8; p++) {
                int idx = tid + p * 256;
                int d = idx >> 3, c = idx & 7;
                cpa16(sb + A_KT + nb * 36864 + (d * 36 + c * 4) * 4,
                      &g_xT[((size_t)(b * 256 + d)) * 1024 + (j1 >> 1) + c * 4]);
            }
            if (tid < 16) cpa16(sb + A_SU + nb * 256 + tid * 16, &g_su[bbase + j1 + tid * 4]);
            CP_COMMIT();
        }

        // ---- S = Y @ K^T : tf32, warp tile 32x16, K=256; ldmatrix frags ----
        float accS[2][2][4];
        #pragma unroll
        for (int mi = 0; mi < 2; mi++)
            #pragma unroll
            for (int ni = 0; ni < 2; ni++)
                #pragma unroll
                for (int q = 0; q < 4; q++) accS[mi][ni][q] = 0.f;
        #pragma unroll 8
        for (int ks = 0; ks < 32; ks++) {
            uint32_t a0[4], a1[4], bq[4];
            ldsm4(a0, aY0 + ks * 32);
            ldsm4(a1, aY1 + ks * 32);
            ldsm4(bq, aKB + ks * 32);
            mma_tf32(accS[0][0], a0, bq);
            mma_tf32(accS[0][1], a0, bq + 2);
            mma_tf32(accS[1][0], a1, bq);
            mma_tf32(accS[1][1], a1, bq + 2);
        }

        // ---- epilogue: P = bf16(exp(S + su)), row sums ----
        #pragma unroll
        for (int mi = 0; mi < 2; mi++)
            #pragma unroll
            for (int ni = 0; ni < 2; ni++) {
                const int c01 = wsc * 16 + ni * 8 + 2 * t;
                const float s0 = su_s[buf * 64 + c01], s1 = su_s[buf * 64 + c01 + 1];
                float p0 = __expf(accS[mi][ni][0] + s0);
                float p1 = __expf(accS[mi][ni][1] + s1);
                float p2 = __expf(accS[mi][ni][2] + s0);
                float p3 = __expf(accS[mi][ni][3] + s1);
                lsum[mi][0] += p0 + p1;
                lsum[mi][1] += p2 + p3;
                const int row = wsr * 32 + mi * 16 + g;
                const int jw = wsc * 8 + ni * 4 + t;
                Pw[row * 36 + jw]       = pk(p0, p1);
                Pw[(row + 8) * 36 + jw] = pk(p2, p3);
            }
        __syncthreads();                 // P visible; S-phase K reads done

        if (tt < NT - 1) {               // K(t+1) cp.async — overlaps PV phase
            const int j1 = (tt + 1) * BN;
            #pragma unroll
            for (int p = 0; p < 16; p++) {
                int idx = tid + p * 256;
                int r = idx >> 6, c4 = idx & 63;
                cpa16(sb + A_KS + (r * 260 + c4 * 4) * 4,
                      &g_h[((size_t)(bbase + j1 + r)) * 512 + c4 * 4]);
            }
            CP_COMMIT();
        }

        // ---- O^T += K^T @ P^T : bf16, warp tile 64d x 32i; ldmatrix frags ----
        const uint32_t tOfs = aT0 + (uint32_t)(buf * 36864);
        #pragma unroll
        for (int kj = 0; kj < 4; kj++) {
            const uint32_t jb = (uint32_t)(kj * 32);   // jw0*4 bytes
            uint32_t a[4][4], bp0[4], bp1[4];
            #pragma unroll
            for (int mi = 0; mi < 4; mi++) ldsm4(a[mi], tOfs + mi * 2304 + jb);
            ldsm4(bp0, aP0 + jb);
            ldsm4(bp1, aP0 + 2304 + jb);
            #pragma unroll
            for (int mi = 0; mi < 4; mi++) {
                mma_bf16(accO[mi][0], a[mi], bp0);
                mma_bf16(accO[mi][1], a[mi], bp0 + 2);
                mma_bf16(accO[mi][2], a[mi], bp1);
                mma_bf16(accO[mi][3], a[mi], bp1 + 2);
            }
        }
    }

    // ---- row-sum reduce ----
    #pragma unroll
    for (int mi = 0; mi < 2; mi++)
        #pragma unroll
        for (int rh = 0; rh < 2; rh++) {
            float v = lsum[mi][rh];
            v += __shfl_xor_sync(0xffffffffu, v, 1);
            v += __shfl_xor_sync(0xffffffffu, v, 2);
            if (t == 0) lsp[wsc * 64 + wsr * 32 + mi * 16 + rh * 8 + g] = v;
        }
    __syncthreads();
    if (tid < 64)
        inv_s[tid] = 1.f / (lsp[tid] + lsp[64 + tid] + lsp[128 + tid] + lsp[192 + tid]);
    __syncthreads();

    // ---- normalize, tf32-round, transpose via shfl, store to g_h attn-half ----
    const bool even = ((g & 1) == 0);
    #pragma unroll
    for (int mi = 0; mi < 4; mi++)
        #pragma unroll
        for (int ni = 0; ni < 4; ni++) {
            const int iA = woc * 32 + ni * 8 + 2 * t;
            const float invA = inv_s[iA], invB = inv_s[iA + 1];
            float c0 = f2tf(accO[mi][ni][0] * invA), c1 = f2tf(accO[mi][ni][1] * invB);
            float c2 = f2tf(accO[mi][ni][2] * invA), c3 = f2tf(accO[mi][ni][3] * invB);
            float v0 = __shfl_xor_sync(0xffffffffu, c0, 4);
            float v1 = __shfl_xor_sync(0xffffffffu, c1, 4);
            float v2 = __shfl_xor_sync(0xffffffffu, c2, 4);
            float v3 = __shfl_xor_sync(0xffffffffu, c3, 4);
            float* rowA = g_h + ((size_t)(bbase + q0 + iA)) * 512 + 256;
            float* rowB = rowA + 512;
            if (even) {
                const int d2 = (wor * 32 + mi * 8 + (g >> 1)) * 2;
                *(float2*)(rowA + d2) = make_float2(c0, v0);
                *(float2*)(rowB + d2) = make_float2(c1, v1);
            } else {
                const int d2 = (wor * 32 + mi * 8 + ((g + 7) >> 1)) * 2;
                *(float2*)(rowA + d2) = make_float2(v2, c2);
                *(float2*)(rowB + d2) = make_float2(v3, c3);
            }
        }
}

// ===========================================================================
// MLP tf32: grid (128, 4), 256 thr; ldmatrix fragment loads.
// ===========================================================================
#define M_HS 0          // [2][128][36] f32 = 36864
#define M_WS 36864      // [2][192][36] f32 = 55296
#define M_END 92160

__global__ __launch_bounds__(256, 1)
void mlp_kernel(const float* __restrict__ x,
                const float* __restrict__ b1, const float* __restrict__ b2,
                const float* __restrict__ b3, float* __restrict__ out)
{
    extern __shared__ char smem[];
    const uint32_t sb = smem_u32(smem);

    const int tid = threadIdx.x, w = tid >> 5, lane = tid & 31;
    const int g = lane >> 2, t = lane & 3;
    const int mw = w >> 1, nw = w & 1;        // 4 m-warps x 2 n-warps
    const int row0 = blockIdx.x * 128, n0 = blockIdx.y * 64;

    const int l7  = lane & 7;
    const int l8h = (lane >> 3) & 1;
    const int l16 = lane >> 4;
    const uint32_t aH0 = sb + M_HS + (uint32_t)(((mw * 32 + l7 + l8h * 8) * 36 + l16 * 4) * 4);
    const uint32_t aW0 = sb + M_WS + (uint32_t)(((nw * 32 + l16 * 8 + l7) * 36 + l8h * 4) * 4);

    // chunk 0: H k=0..31, W k=0..31
    #pragma unroll
    for (int p = 0; p < 4; p++) {
        int idx = tid + p * 256;
        int r = idx >> 3, c = idx & 7;
        cpa16(sb + M_HS + (r * 36 + c * 4) * 4,
              &g_h[((size_t)(row0 + r)) * 512 + c * 4]);
    }
    #pragma unroll
    for (int p = 0; p < 6; p++) {
        int idx = tid + p * 256;
        int m = idx >> 9, rem = idx & 511;
        int n = rem >> 3, c = rem & 7;
        cpa16(sb + M_WS + ((m * 64 + n) * 36 + c * 4) * 4,
              &g_wtf[((size_t)m * 256 + n0 + n) * 512 + c * 4]);
    }
    CP_COMMIT();

    float acc[3][2][4][4];
    #pragma unroll
    for (int m = 0; m < 3; m++)
        #pragma unroll
        for (int mi = 0; mi < 2; mi++)
            #pragma unroll
            for (int ni = 0; ni < 4; ni++)
                #pragma unroll
                for (int q = 0; q < 4; q++) acc[m][mi][ni][q] = 0.f;

    for (int s = 0; s < 16; s++) {
        CP_WAIT0();
        __syncthreads();
        const int buf = s & 1;

        if (s < 15) {
            const int nb = (s + 1) & 1, k1 = (s + 1) * 32;
            #pragma unroll
            for (int p = 0; p < 4; p++) {
                int idx = tid + p * 256;
                int r = idx >> 3, c = idx & 7;
                cpa16(sb + M_HS + nb * 18432 + (r * 36 + c * 4) * 4,
                      &g_h[((size_t)(row0 + r)) * 512 + k1 + c * 4]);
            }
            #pragma unroll
            for (int p = 0; p < 6; p++) {
                int idx = tid + p * 256;
                int m = idx >> 9, rem = idx & 511;
                int n = rem >> 3, c = rem & 7;
                cpa16(sb + M_WS + nb * 27648 + ((m * 64 + n) * 36 + c * 4) * 4,
                      &g_wtf[((size_t)m * 256 + n0 + n) * 512 + k1 + c * 4]);
            }
            CP_COMMIT();
        }

        const uint32_t hOfs = aH0 + (uint32_t)(buf * 18432);
        const uint32_t wOfs = aW0 + (uint32_t)(buf * 27648);
        #pragma unroll
        for (int ks = 0; ks < 4; ks++) {
            const uint32_t kb = (uint32_t)(ks * 32);
            uint32_t a0[4], a1[4];
            ldsm4(a0, hOfs + kb);
            ldsm4(a1, hOfs + 16 * 36 * 4 + kb);
            #pragma unroll
            for (int m = 0; m < 3; m++) {
                uint32_t bq0[4], bq1[4];
                ldsm4(bq0, wOfs + m * 9216 + kb);
                ldsm4(bq1, wOfs + m * 9216 + 2304 + kb);
                mma_tf32(acc[m][0][0], a0, bq0);
                mma_tf32(acc[m][0][1], a0, bq0 + 2);
                mma_tf32(acc[m][0][2], a0, bq1);
                mma_tf32(acc[m][0][3], a0, bq1 + 2);
                mma_tf32(acc[m][1][0], a1, bq0);
                mma_tf32(acc[m][1][1], a1, bq0 + 2);
                mma_tf32(acc[m][1][2], a1, bq1);
                mma_tf32(acc[m][1][3], a1, bq1 + 2);
            }
        }
    }

    // fused epilogue
    #pragma unroll
    for (int mi = 0; mi < 2; mi++)
        #pragma unroll
        for (int ni = 0; ni < 4; ni++) {
            const int rloc = mw * 32 + mi * 16 + g;
            const int cc = n0 + nw * 32 + ni * 8 + 2 * t;
            const float2 bb1 = *(const float2*)(b1 + cc);
            const float2 bb2 = *(const float2*)(b2 + cc);
            const float2 bb3 = *(const float2*)(b3 + cc);
            #pragma unroll
            for (int h = 0; h < 2; h++) {
                const int rl = rloc + h * 8, i0 = h * 2;
                float z0 = tanhf(acc[0][mi][ni][i0]     + bb1.x);
                float z1 = tanhf(acc[0][mi][ni][i0 + 1] + bb1.y);
                float r0 = 1.f / (1.f + __expf(-(acc[1][mi][ni][i0]     + bb2.x)));
                float r1 = 1.f / (1.f + __expf(-(acc[1][mi][ni][i0 + 1] + bb2.y)));
                float f0 = 1.f / (1.f + __expf(-(acc[2][mi][ni][i0]     + bb3.x)));
                float f1 = 1.f / (1.f + __expf(-(acc[2][mi][ni][i0 + 1] + bb3.y)));
                const float2 xv = *(const float2*)(x + (size_t)(row0 + rl) * DD + cc);
                float2 o = make_float2(r0 * xv.x + f0 * z0, r1 * xv.y + f1 * z1);
                *(float2*)(out + (size_t)(row0 + rl) * DD + cc) = o;
            }
        }
}

// ===========================================================================
extern "C" void kernel_launch(void* const* d_in, const int* in_sizes, int n_in,
                              void* d_out, int out_size)
{
    const float* x   = (const float*)d_in[0];
    const float* wia = (const float*)d_in[1];
    const float* w1  = (const float*)d_in[2];
    const float* w2  = (const float*)d_in[3];
    const float* w3  = (const float*)d_in[4];
    const float* b1  = (const float*)d_in[5];
    const float* b2  = (const float*)d_in[6];
    const float* b3  = (const float*)d_in[7];
    float* out = (float*)d_out;

    cudaFuncSetAttribute(attn_kernel, cudaFuncAttributeMaxDynamicSharedMemorySize, A_END);
    cudaFuncSetAttribute(mlp_kernel,  cudaFuncAttributeMaxDynamicSharedMemorySize, M_END);

    prep_su  <<<LL * BB / 8, 256>>>(x, wia);
    prep_pack<<<BB * 128, 256>>>(x, wia);
    prep_w   <<<96, 256>>>(w1, w2, w3);
    attn_kernel<<<dim3(LL / BM, BB), 256, A_END>>>();
    mlp_kernel <<<dim3(BB * LL / 128, 4), 256, M_END>>>(x, b1, b2, b3, out);
}